// round 7
// baseline (speedup 1.0000x reference)
#include <cuda_runtime.h>
#include <cuda_bf16.h>

#define B_  8192
#define T_  200
#define IN_ 4
#define H_  16
#define L_  4
#define MLP_IN  (H_ * T_)   // 3200
#define MLP_HID 64
#define MLP_OUT 28
#define NCHUNK  16          // mlp1 K-chunks (200 rows each)

typedef unsigned long long ull;

// ---------------- scratch (no allocations allowed) ----------------
__device__ float g_h3[(long)MLP_IN * B_];                 // [m][b]
__device__ float g_partial[NCHUNK * MLP_HID * B_];        // [chunk][j][b]

// ---------------- packed f32x2 helpers ----------------
__device__ __forceinline__ ull pack2(float lo, float hi) {
    ull r; asm("mov.b64 %0, {%1, %2};" : "=l"(r) : "f"(lo), "f"(hi)); return r;
}
__device__ __forceinline__ void unpack2(ull v, float& lo, float& hi) {
    asm("mov.b64 {%0, %1}, %2;" : "=f"(lo), "=f"(hi) : "l"(v));
}
__device__ __forceinline__ ull ffma2(ull a, ull b, ull c) {
    ull d; asm("fma.rn.f32x2 %0, %1, %2, %3;" : "=l"(d) : "l"(a), "l"(b), "l"(c)); return d;
}

// ---------------- activations (fp32, overflow-safe) ----------------
__device__ __forceinline__ float sigmoidf_(float x) {
    return __fdividef(1.0f, 1.0f + __expf(-x));
}
__device__ __forceinline__ float tanhf_(float x) {
    float e = __expf(-2.0f * fabsf(x));           // in (0, 1], never overflows
    float t = __fdividef(1.0f - e, 1.0f + e);
    return copysignf(t, x);
}

// =====================================================================
// LSTM kernel: 1 hidden unit per thread, E=4 batch elems per thread.
// Warp = 2 groups of 16 lanes; lane sub (0..15) owns unit j=sub.
// 128 CTAs x 256 = 32768 threads = 8 warps/SM (2 per SMSP).
// Gate math packed as f32x2: acc pairs (i,f) and (g,o).
// =====================================================================
__global__ void __launch_bounds__(256) lstm_kernel(
    const float* __restrict__ x,         // [B, T, IN]
    const float* __restrict__ Wih0,      // [64, 4]
    const float* __restrict__ Wih_rest,  // [3, 64, 16]
    const float* __restrict__ Whh,       // [4, 64, 16]
    const float* __restrict__ bih,       // [4, 64]
    const float* __restrict__ bhh)       // [4, 64]
{
    __shared__ float4 Whr4[L_ * 16 * 16];   // [(l*16 + k)*16 + j] -> gates i,f,g,o
    __shared__ float4 Wir4[L_ * 16 * 16];   // same layout (layer0 uses d<4 only)
    __shared__ float4 bias4[L_ * 16];       // [(l*16 + j)] -> gates

    {
        float* whr = reinterpret_cast<float*>(Whr4);
        float* wir = reinterpret_cast<float*>(Wir4);
        for (int idx = threadIdx.x; idx < L_ * 16 * 16 * 4; idx += blockDim.x) {
            int g = idx & 3;
            int j = (idx >> 2) & 15;
            int k = (idx >> 6) & 15;
            int l = idx >> 10;
            whr[idx] = Whh[l * 1024 + (g * 16 + j) * 16 + k];
            float wv;
            if (l == 0) wv = (k < IN_) ? Wih0[(g * 16 + j) * IN_ + k] : 0.0f;
            else        wv = Wih_rest[(l - 1) * 1024 + (g * 16 + j) * 16 + k];
            wir[idx] = wv;
        }
        float* bb = reinterpret_cast<float*>(bias4);
        for (int idx = threadIdx.x; idx < L_ * 16 * 4; idx += blockDim.x) {
            int g = idx & 3;
            int j = (idx >> 2) & 15;
            int l = idx >> 6;
            bb[idx] = bih[l * 64 + g * 16 + j] + bhh[l * 64 + g * 16 + j];
        }
    }
    __syncthreads();

    const int lane = threadIdx.x & 31;
    const int sub  = lane & 15;                // owned hidden unit j
    const int grpb = lane & 16;                // base lane of 16-lane group
    const int b0   = blockIdx.x * 64 + (threadIdx.x >> 4) * 4;  // elems b0..b0+3

    float h_own[L_][4];   // [layer][elem]
    float c_own[L_][4];
#pragma unroll
    for (int l = 0; l < L_; ++l)
#pragma unroll
        for (int e = 0; e < 4; ++e) { h_own[l][e] = 0.0f; c_own[l][e] = 0.0f; }

    for (int t = 0; t < T_; ++t) {
        float xq[4][4];
#pragma unroll
        for (int e = 0; e < 4; ++e) {
            float4 v = *reinterpret_cast<const float4*>(x + ((long)(b0 + e) * T_ + t) * IN_);
            xq[e][0] = v.x; xq[e][1] = v.y; xq[e][2] = v.z; xq[e][3] = v.w;
        }

#pragma unroll
        for (int l = 0; l < L_; ++l) {
            float4 bb = bias4[l * 16 + sub];
            ull aIF[4], aGO[4];                 // packed (i,f) and (g,o) per elem
            {
                ull bIF = pack2(bb.x, bb.y);
                ull bGO = pack2(bb.z, bb.w);
#pragma unroll
                for (int e = 0; e < 4; ++e) { aIF[e] = bIF; aGO[e] = bGO; }
            }

            // ---- input projection ----
            if (l == 0) {
#pragma unroll
                for (int k = 0; k < IN_; ++k) {
                    float4 w = Wir4[(0 * 16 + k) * 16 + sub];
                    ull wIF = pack2(w.x, w.y);
                    ull wGO = pack2(w.z, w.w);
#pragma unroll
                    for (int e = 0; e < 4; ++e) {
                        ull h2 = pack2(xq[e][k], xq[e][k]);
                        aIF[e] = ffma2(wIF, h2, aIF[e]);
                        aGO[e] = ffma2(wGO, h2, aGO[e]);
                    }
                }
            } else {
#pragma unroll
                for (int k = 0; k < 16; ++k) {
                    float4 w = Wir4[(l * 16 + k) * 16 + sub];
                    ull wIF = pack2(w.x, w.y);
                    ull wGO = pack2(w.z, w.w);
#pragma unroll
                    for (int e = 0; e < 4; ++e) {
                        float hx = __shfl_sync(0xffffffffu, h_own[l - 1][e], grpb | k);
                        ull h2 = pack2(hx, hx);
                        aIF[e] = ffma2(wIF, h2, aIF[e]);
                        aGO[e] = ffma2(wGO, h2, aGO[e]);
                    }
                }
            }

            // ---- recurrent projection (h_own[l] is still t-1 state) ----
#pragma unroll
            for (int k = 0; k < 16; ++k) {
                float4 w = Whr4[(l * 16 + k) * 16 + sub];
                ull wIF = pack2(w.x, w.y);
                ull wGO = pack2(w.z, w.w);
#pragma unroll
                for (int e = 0; e < 4; ++e) {
                    float hx = __shfl_sync(0xffffffffu, h_own[l][e], grpb | k);
                    ull h2 = pack2(hx, hx);
                    aIF[e] = ffma2(wIF, h2, aIF[e]);
                    aGO[e] = ffma2(wGO, h2, aGO[e]);
                }
            }

            // ---- activations + state update ----
#pragma unroll
            for (int e = 0; e < 4; ++e) {
                float ai, af, ag, ao;
                unpack2(aIF[e], ai, af);
                unpack2(aGO[e], ag, ao);
                float iv = sigmoidf_(ai);
                float fv = sigmoidf_(af);
                float gv = tanhf_(ag);
                float ov = sigmoidf_(ao);
                float cv = fmaf(fv, c_own[l][e], iv * gv);
                c_own[l][e] = cv;
                h_own[l][e] = ov * tanhf_(cv);
            }
        }

        float4 v = make_float4(h_own[L_ - 1][0], h_own[L_ - 1][1],
                               h_own[L_ - 1][2], h_own[L_ - 1][3]);
        *reinterpret_cast<float4*>(g_h3 + (long)(t * 16 + sub) * B_ + b0) = v;
    }
}

// =====================================================================
// MLP phase 1: partial hid sums over NCHUNK chunks of 200 rows.
// grid (32 b-blocks of 256 elems, 16 chunks) x 256 threads.
// Thread owns 4 batch elems x 16 j; packed f32x2 FMA on j-pairs.
// =====================================================================
__global__ void __launch_bounds__(256) mlp1_kernel(const float* __restrict__ W1)
{
    __shared__ float4 W1s[200 * 16];   // [mm][j4], 51.2 KB
    const int chunk = blockIdx.y;
    const int m0 = chunk * 200;
    {
        float* w = reinterpret_cast<float*>(W1s);
        for (int idx = threadIdx.x; idx < 200 * MLP_HID; idx += blockDim.x) {
            int mm = idx >> 6, j = idx & 63;
            w[idx] = W1[j * MLP_IN + m0 + mm];
        }
    }
    __syncthreads();

    const int jq = threadIdx.x & 3;           // j quarter: js 16*jq .. 16*jq+15
    const int bq = threadIdx.x >> 2;          // 64 quads per CTA
    const int b0 = blockIdx.x * 256 + bq * 4; // elems b0..b0+3

    ull acc[8][4];                             // [j-pair][elem]
#pragma unroll
    for (int jp = 0; jp < 8; ++jp)
#pragma unroll
        for (int e = 0; e < 4; ++e) acc[jp][e] = 0ull;

    for (int mm = 0; mm < 200; ++mm) {
        float4 f = *reinterpret_cast<const float4*>(g_h3 + (long)(m0 + mm) * B_ + b0);
        ull f2[4] = { pack2(f.x, f.x), pack2(f.y, f.y), pack2(f.z, f.z), pack2(f.w, f.w) };
#pragma unroll
        for (int j4 = 0; j4 < 4; ++j4) {
            float4 w = W1s[mm * 16 + jq * 4 + j4];
            ull w01 = pack2(w.x, w.y);
            ull w23 = pack2(w.z, w.w);
#pragma unroll
            for (int e = 0; e < 4; ++e) {
                acc[j4 * 2 + 0][e] = ffma2(w01, f2[e], acc[j4 * 2 + 0][e]);
                acc[j4 * 2 + 1][e] = ffma2(w23, f2[e], acc[j4 * 2 + 1][e]);
            }
        }
    }
#pragma unroll
    for (int jp = 0; jp < 8; ++jp) {
        float v0[4], v1[4];
#pragma unroll
        for (int e = 0; e < 4; ++e) unpack2(acc[jp][e], v0[e], v1[e]);
        int j = jq * 16 + jp * 2;
        *reinterpret_cast<float4*>(g_partial + ((long)chunk * MLP_HID + j) * B_ + b0) =
            make_float4(v0[0], v0[1], v0[2], v0[3]);
        *reinterpret_cast<float4*>(g_partial + ((long)chunk * MLP_HID + j + 1) * B_ + b0) =
            make_float4(v1[0], v1[1], v1[2], v1[3]);
    }
}

// =====================================================================
// MLP phase 2: reduce chunks, bias+relu, W2, write out [B, 28].
// =====================================================================
__global__ void __launch_bounds__(256) mlp2_kernel(
    const float* __restrict__ W2,   // [28, 64]
    const float* __restrict__ b1,   // [64]
    const float* __restrict__ b2,   // [28]
    float* __restrict__ out)        // [B, 28]
{
    __shared__ float W2s[MLP_OUT * MLP_HID];
    __shared__ float b1s[MLP_HID];
    __shared__ float b2s[MLP_OUT];
    for (int idx = threadIdx.x; idx < MLP_OUT * MLP_HID; idx += blockDim.x)
        W2s[idx] = W2[idx];
    if (threadIdx.x < MLP_HID) b1s[threadIdx.x] = b1[threadIdx.x];
    if (threadIdx.x < MLP_OUT) b2s[threadIdx.x] = b2[threadIdx.x];
    __syncthreads();

    const int b = blockIdx.x * 256 + threadIdx.x;
    float hid[MLP_HID];
#pragma unroll
    for (int j = 0; j < MLP_HID; ++j) hid[j] = b1s[j];

    for (int ch = 0; ch < NCHUNK; ++ch) {
#pragma unroll
        for (int j = 0; j < MLP_HID; ++j)
            hid[j] += g_partial[((long)ch * MLP_HID + j) * B_ + b];
    }
#pragma unroll
    for (int j = 0; j < MLP_HID; ++j) hid[j] = fmaxf(hid[j], 0.0f);

#pragma unroll
    for (int o = 0; o < MLP_OUT; ++o) {
        float a = b2s[o];
#pragma unroll
        for (int j = 0; j < MLP_HID; ++j)
            a = fmaf(hid[j], W2s[o * MLP_HID + j], a);
        out[(long)b * MLP_OUT + o] = a;
    }
}

// =====================================================================
extern "C" void kernel_launch(void* const* d_in, const int* in_sizes, int n_in,
                              void* d_out, int out_size)
{
    const float* x        = (const float*)d_in[0];
    const float* Wih0     = (const float*)d_in[1];
    const float* Wih_rest = (const float*)d_in[2];
    const float* Whh      = (const float*)d_in[3];
    const float* bih      = (const float*)d_in[4];
    const float* bhh      = (const float*)d_in[5];
    const float* W1       = (const float*)d_in[6];
    const float* b1       = (const float*)d_in[7];
    const float* W2       = (const float*)d_in[8];
    const float* b2       = (const float*)d_in[9];
    float* out = (float*)d_out;

    lstm_kernel<<<128, 256>>>(x, Wih0, Wih_rest, Whh, bih, bhh);
    mlp1_kernel<<<dim3(32, NCHUNK), 256>>>(W1);
    mlp2_kernel<<<32, 256>>>(W2, b1, b2, out);
}

// round 8
// speedup vs baseline: 1.0669x; 1.0669x over previous
#include <cuda_runtime.h>
#include <cuda_bf16.h>

#define B_  8192
#define T_  200
#define IN_ 4
#define H_  16
#define L_  4
#define MLP_IN  (H_ * T_)   // 3200
#define MLP_HID 64
#define MLP_OUT 28
#define NCHUNK  16          // mlp1 K-chunks (200 rows each)

typedef unsigned long long ull;

// ---------------- scratch (no allocations allowed) ----------------
__device__ float g_h3[(long)MLP_IN * B_];                 // [m][b]
__device__ float g_partial[NCHUNK * MLP_HID * B_];        // [chunk][j][b]

// ---------------- packed f32x2 helpers ----------------
__device__ __forceinline__ ull pack2(float lo, float hi) {
    ull r; asm("mov.b64 %0, {%1, %2};" : "=l"(r) : "f"(lo), "f"(hi)); return r;
}
__device__ __forceinline__ void unpack2(ull v, float& lo, float& hi) {
    asm("mov.b64 {%0, %1}, %2;" : "=f"(lo), "=f"(hi) : "l"(v));
}
__device__ __forceinline__ ull ffma2(ull a, ull b, ull c) {
    ull d; asm("fma.rn.f32x2 %0, %1, %2, %3;" : "=l"(d) : "l"(a), "l"(b), "l"(c)); return d;
}

// ---------------- activations (fp32, overflow-safe) ----------------
__device__ __forceinline__ float sigmoidf_(float x) {
    return __fdividef(1.0f, 1.0f + __expf(-x));
}
__device__ __forceinline__ float tanhf_(float x) {
    float e = __expf(-2.0f * fabsf(x));           // in (0, 1], never overflows
    float t = __fdividef(1.0f - e, 1.0f + e);
    return copysignf(t, x);
}

// hbuf layout: ull hbuf[ ((w*4 + l)*4 + e)*40 + g*20 + k ]
//   per (w,l,e): group 0 at +0 (16 ull = 128B), group 1 at +160B (pad 4 -> bank shift 8)
//   each entry = (h,h) duplicated f32x2 pair.
#define HB_STRIDE_E 40
#define HB_STRIDE_G 20
#define HB_TOTAL    (8 * 4 * 4 * HB_STRIDE_E)   // 5120 ull = 40 KB

// =====================================================================
// LSTM: 1 unit/thread, E=4 elems/thread. Warp = 2 groups of 16 lanes.
// 128 CTAs x 256 threads = 8 warps/SM. h exchanged via per-warp smem
// regions with broadcast LDS.128 reads (no shfl, no pack movs).
// =====================================================================
__global__ void __launch_bounds__(256) lstm_kernel(
    const float* __restrict__ x,         // [B, T, IN]
    const float* __restrict__ Wih0,      // [64, 4]
    const float* __restrict__ Wih_rest,  // [3, 64, 16]
    const float* __restrict__ Whh,       // [4, 64, 16]
    const float* __restrict__ bih,       // [4, 64]
    const float* __restrict__ bhh)       // [4, 64]
{
    __shared__ float4 Whr4[L_ * 16 * 16];   // [(l*16 + k)*16 + j] -> gates i,f,g,o
    __shared__ float4 Wir4[L_ * 16 * 16];   // same layout (layer0 uses d<4 only)
    __shared__ float4 bias4[L_ * 16];       // [(l*16 + j)] -> gates
    extern __shared__ ull hbuf[];           // 40 KB dynamic

    {
        float* whr = reinterpret_cast<float*>(Whr4);
        float* wir = reinterpret_cast<float*>(Wir4);
        for (int idx = threadIdx.x; idx < L_ * 16 * 16 * 4; idx += blockDim.x) {
            int g = idx & 3;
            int j = (idx >> 2) & 15;
            int k = (idx >> 6) & 15;
            int l = idx >> 10;
            whr[idx] = Whh[l * 1024 + (g * 16 + j) * 16 + k];
            float wv;
            if (l == 0) wv = (k < IN_) ? Wih0[(g * 16 + j) * IN_ + k] : 0.0f;
            else        wv = Wih_rest[(l - 1) * 1024 + (g * 16 + j) * 16 + k];
            wir[idx] = wv;
        }
        float* bb = reinterpret_cast<float*>(bias4);
        for (int idx = threadIdx.x; idx < L_ * 16 * 4; idx += blockDim.x) {
            int g = idx & 3;
            int j = (idx >> 2) & 15;
            int l = idx >> 6;
            bb[idx] = bih[l * 64 + g * 16 + j] + bhh[l * 64 + g * 16 + j];
        }
        for (int i = threadIdx.x; i < HB_TOTAL; i += blockDim.x) hbuf[i] = 0ull;
    }
    __syncthreads();

    const int w    = threadIdx.x >> 5;
    const int g    = (threadIdx.x >> 4) & 1;
    const int sub  = threadIdx.x & 15;               // owned hidden unit j
    const int b0   = blockIdx.x * 64 + (threadIdx.x >> 4) * 4;  // elems b0..b0+3
    const int hb_g = g * HB_STRIDE_G;

    float c_own[L_][4];
#pragma unroll
    for (int l = 0; l < L_; ++l)
#pragma unroll
        for (int e = 0; e < 4; ++e) c_own[l][e] = 0.0f;

    for (int t = 0; t < T_; ++t) {
        float xq[4][4];
#pragma unroll
        for (int e = 0; e < 4; ++e) {
            float4 v = *reinterpret_cast<const float4*>(x + ((long)(b0 + e) * T_ + t) * IN_);
            xq[e][0] = v.x; xq[e][1] = v.y; xq[e][2] = v.z; xq[e][3] = v.w;
        }

#pragma unroll
        for (int l = 0; l < L_; ++l) {
            ulonglong2 bb = *reinterpret_cast<const ulonglong2*>(&bias4[l * 16 + sub]);
            ull aIF[4], aGO[4];
#pragma unroll
            for (int e = 0; e < 4; ++e) { aIF[e] = bb.x; aGO[e] = bb.y; }

            // ---- input projection ----
            if (l == 0) {
#pragma unroll
                for (int k = 0; k < IN_; ++k) {
                    ulonglong2 wp = *reinterpret_cast<const ulonglong2*>(&Wir4[k * 16 + sub]);
#pragma unroll
                    for (int e = 0; e < 4; ++e) {
                        ull h2 = pack2(xq[e][k], xq[e][k]);
                        aIF[e] = ffma2(wp.x, h2, aIF[e]);
                        aGO[e] = ffma2(wp.y, h2, aGO[e]);
                    }
                }
            } else {
                const int hb_l = (w * 4 + (l - 1)) * 4;   // region of layer l-1 (new h)
#pragma unroll
                for (int q = 0; q < 8; ++q) {
                    ulonglong2 hp[4];
#pragma unroll
                    for (int e = 0; e < 4; ++e)
                        hp[e] = *reinterpret_cast<const ulonglong2*>(
                            &hbuf[(hb_l + e) * HB_STRIDE_E + hb_g + 2 * q]);
#pragma unroll
                    for (int kk = 0; kk < 2; ++kk) {
                        int k = 2 * q + kk;
                        ulonglong2 wp = *reinterpret_cast<const ulonglong2*>(
                            &Wir4[(l * 16 + k) * 16 + sub]);
#pragma unroll
                        for (int e = 0; e < 4; ++e) {
                            ull h2 = kk ? hp[e].y : hp[e].x;
                            aIF[e] = ffma2(wp.x, h2, aIF[e]);
                            aGO[e] = ffma2(wp.y, h2, aGO[e]);
                        }
                    }
                }
            }

            // ---- recurrent projection (region l holds t-1 state) ----
            {
                const int hb_l = (w * 4 + l) * 4;
#pragma unroll
                for (int q = 0; q < 8; ++q) {
                    ulonglong2 hp[4];
#pragma unroll
                    for (int e = 0; e < 4; ++e)
                        hp[e] = *reinterpret_cast<const ulonglong2*>(
                            &hbuf[(hb_l + e) * HB_STRIDE_E + hb_g + 2 * q]);
#pragma unroll
                    for (int kk = 0; kk < 2; ++kk) {
                        int k = 2 * q + kk;
                        ulonglong2 wp = *reinterpret_cast<const ulonglong2*>(
                            &Whr4[(l * 16 + k) * 16 + sub]);
#pragma unroll
                        for (int e = 0; e < 4; ++e) {
                            ull h2 = kk ? hp[e].y : hp[e].x;
                            aIF[e] = ffma2(wp.x, h2, aIF[e]);
                            aGO[e] = ffma2(wp.y, h2, aGO[e]);
                        }
                    }
                }
            }

            // ---- activations + state update ----
            float hn[4];
#pragma unroll
            for (int e = 0; e < 4; ++e) {
                float ai, af, ag, ao;
                unpack2(aIF[e], ai, af);
                unpack2(aGO[e], ag, ao);
                float iv = sigmoidf_(ai);
                float fv = sigmoidf_(af);
                float gv = tanhf_(ag);
                float ov = sigmoidf_(ao);
                float cv = fmaf(fv, c_own[l][e], iv * gv);
                c_own[l][e] = cv;
                hn[e] = ov * tanhf_(cv);
            }

            // ---- publish new h (after all lanes finished reading old h) ----
            __syncwarp();
            {
                const int hb_l = (w * 4 + l) * 4;
#pragma unroll
                for (int e = 0; e < 4; ++e)
                    hbuf[(hb_l + e) * HB_STRIDE_E + hb_g + sub] = pack2(hn[e], hn[e]);
            }
            __syncwarp();

            if (l == L_ - 1) {
                float4 v = make_float4(hn[0], hn[1], hn[2], hn[3]);
                *reinterpret_cast<float4*>(g_h3 + (long)(t * 16 + sub) * B_ + b0) = v;
            }
        }
    }
}

// =====================================================================
// MLP phase 1: partial hid sums over NCHUNK chunks of 200 rows.
// =====================================================================
__global__ void __launch_bounds__(256) mlp1_kernel(const float* __restrict__ W1)
{
    __shared__ float4 W1s[200 * 16];   // [mm][j4], 51.2 KB
    const int chunk = blockIdx.y;
    const int m0 = chunk * 200;
    {
        float* w = reinterpret_cast<float*>(W1s);
        for (int idx = threadIdx.x; idx < 200 * MLP_HID; idx += blockDim.x) {
            int mm = idx >> 6, j = idx & 63;
            w[idx] = W1[j * MLP_IN + m0 + mm];
        }
    }
    __syncthreads();

    const int jq = threadIdx.x & 3;
    const int bq = threadIdx.x >> 2;
    const int b0 = blockIdx.x * 256 + bq * 4;

    ull acc[8][4];
#pragma unroll
    for (int jp = 0; jp < 8; ++jp)
#pragma unroll
        for (int e = 0; e < 4; ++e) acc[jp][e] = 0ull;

    for (int mm = 0; mm < 200; ++mm) {
        float4 f = *reinterpret_cast<const float4*>(g_h3 + (long)(m0 + mm) * B_ + b0);
        ull f2[4] = { pack2(f.x, f.x), pack2(f.y, f.y), pack2(f.z, f.z), pack2(f.w, f.w) };
#pragma unroll
        for (int j4 = 0; j4 < 4; ++j4) {
            ulonglong2 wp = *reinterpret_cast<const ulonglong2*>(&W1s[mm * 16 + jq * 4 + j4]);
#pragma unroll
            for (int e = 0; e < 4; ++e) {
                acc[j4 * 2 + 0][e] = ffma2(wp.x, f2[e], acc[j4 * 2 + 0][e]);
                acc[j4 * 2 + 1][e] = ffma2(wp.y, f2[e], acc[j4 * 2 + 1][e]);
            }
        }
    }
#pragma unroll
    for (int jp = 0; jp < 8; ++jp) {
        float v0[4], v1[4];
#pragma unroll
        for (int e = 0; e < 4; ++e) unpack2(acc[jp][e], v0[e], v1[e]);
        int j = jq * 16 + jp * 2;
        *reinterpret_cast<float4*>(g_partial + ((long)chunk * MLP_HID + j) * B_ + b0) =
            make_float4(v0[0], v0[1], v0[2], v0[3]);
        *reinterpret_cast<float4*>(g_partial + ((long)chunk * MLP_HID + j + 1) * B_ + b0) =
            make_float4(v1[0], v1[1], v1[2], v1[3]);
    }
}

// =====================================================================
// MLP phase 2: reduce chunks, bias+relu, W2, write out [B, 28].
// =====================================================================
__global__ void __launch_bounds__(256) mlp2_kernel(
    const float* __restrict__ W2,   // [28, 64]
    const float* __restrict__ b1,   // [64]
    const float* __restrict__ b2,   // [28]
    float* __restrict__ out)        // [B, 28]
{
    __shared__ float W2s[MLP_OUT * MLP_HID];
    __shared__ float b1s[MLP_HID];
    __shared__ float b2s[MLP_OUT];
    for (int idx = threadIdx.x; idx < MLP_OUT * MLP_HID; idx += blockDim.x)
        W2s[idx] = W2[idx];
    if (threadIdx.x < MLP_HID) b1s[threadIdx.x] = b1[threadIdx.x];
    if (threadIdx.x < MLP_OUT) b2s[threadIdx.x] = b2[threadIdx.x];
    __syncthreads();

    const int b = blockIdx.x * 256 + threadIdx.x;
    float hid[MLP_HID];
#pragma unroll
    for (int j = 0; j < MLP_HID; ++j) hid[j] = b1s[j];

    for (int ch = 0; ch < NCHUNK; ++ch) {
#pragma unroll
        for (int j = 0; j < MLP_HID; ++j)
            hid[j] += g_partial[((long)ch * MLP_HID + j) * B_ + b];
    }
#pragma unroll
    for (int j = 0; j < MLP_HID; ++j) hid[j] = fmaxf(hid[j], 0.0f);

#pragma unroll
    for (int o = 0; o < MLP_OUT; ++o) {
        float a = b2s[o];
#pragma unroll
        for (int j = 0; j < MLP_HID; ++j)
            a = fmaf(hid[j], W2s[o * MLP_HID + j], a);
        out[(long)b * MLP_OUT + o] = a;
    }
}

// =====================================================================
extern "C" void kernel_launch(void* const* d_in, const int* in_sizes, int n_in,
                              void* d_out, int out_size)
{
    const float* x        = (const float*)d_in[0];
    const float* Wih0     = (const float*)d_in[1];
    const float* Wih_rest = (const float*)d_in[2];
    const float* Whh      = (const float*)d_in[3];
    const float* bih      = (const float*)d_in[4];
    const float* bhh      = (const float*)d_in[5];
    const float* W1       = (const float*)d_in[6];
    const float* b1       = (const float*)d_in[7];
    const float* W2       = (const float*)d_in[8];
    const float* b2       = (const float*)d_in[9];
    float* out = (float*)d_out;

    cudaFuncSetAttribute(lstm_kernel, cudaFuncAttributeMaxDynamicSharedMemorySize,
                         HB_TOTAL * (int)sizeof(ull));
    lstm_kernel<<<128, 256, HB_TOTAL * sizeof(ull)>>>(x, Wih0, Wih_rest, Whh, bih, bhh);
    mlp1_kernel<<<dim3(32, NCHUNK), 256>>>(W1);
    mlp2_kernel<<<32, 256>>>(W2, b1, b2, out);
}

// round 10
// speedup vs baseline: 1.1169x; 1.0469x over previous
#include <cuda_runtime.h>
#include <cuda_bf16.h>

#define B_  8192
#define T_  200
#define IN_ 4
#define H_  16
#define L_  4
#define MLP_IN  (H_ * T_)   // 3200
#define MLP_HID 64
#define MLP_OUT 28
#define NCHUNK  16          // mlp1 K-chunks (200 rows each)

typedef unsigned long long ull;

// ---------------- scratch (no allocations allowed) ----------------
__device__ float g_h3[(long)MLP_IN * B_];                 // [m][b]
__device__ float g_partial[NCHUNK * MLP_HID * B_];        // [chunk][j][b]

// ---------------- packed f32x2 helpers ----------------
__device__ __forceinline__ ull pack2(float lo, float hi) {
    ull r; asm("mov.b64 %0, {%1, %2};" : "=l"(r) : "f"(lo), "f"(hi)); return r;
}
__device__ __forceinline__ void unpack2(ull v, float& lo, float& hi) {
    asm("mov.b64 {%0, %1}, %2;" : "=f"(lo), "=f"(hi) : "l"(v));
}
__device__ __forceinline__ ull ffma2(ull a, ull b, ull c) {
    ull d; asm("fma.rn.f32x2 %0, %1, %2, %3;" : "=l"(d) : "l"(a), "l"(b), "l"(c)); return d;
}

// ---------------- activations (fp32, overflow-safe) ----------------
__device__ __forceinline__ float sigmoidf_(float x) {
    return __fdividef(1.0f, 1.0f + __expf(-x));
}
__device__ __forceinline__ float tanhf_(float x) {
    float e = __expf(-2.0f * fabsf(x));           // in (0, 1], never overflows
    float t = __fdividef(1.0f - e, 1.0f + e);
    return copysignf(t, x);
}

// h buffer (dynamic smem): float hb[w][l][e][grp][k]
//   k:16 floats (64B), grp:2, e:4, l:4, w:8  -> 4096 floats = 16 KB
#define HB_GRP 16
#define HB_E   32
#define HB_L   128
#define HB_W   512
#define HB_TOTAL_F (8 * HB_W)

// =====================================================================
// LSTM: 1 unit/thread, E=4 elems/thread. Warp = 2 groups of 16 lanes.
// 128 CTAs x 256 threads = 8 warps/SM.
// FFMA2 packs (even-k, odd-k) partial sums per gate:
//   - h pairs come straight from non-duplicated k-contiguous smem
//   - weight pairs come from [gate][kc][j][4k] float4 layout
// =====================================================================
__global__ void __launch_bounds__(256) lstm_kernel(
    const float* __restrict__ x,         // [B, T, IN]
    const float* __restrict__ Wih0,      // [64, 4]
    const float* __restrict__ Wih_rest,  // [3, 64, 16]
    const float* __restrict__ Whh,       // [4, 64, 16]
    const float* __restrict__ bih,       // [4, 64]
    const float* __restrict__ bhh)       // [4, 64]
{
    // weights: float4 wbuf4[ (((l*2+mat)*4+g)*4+kc)*16 + j ]  (32 KB)
    __shared__ float4 wbuf4[L_ * 2 * 4 * 4 * 16];
    // bias pre-packed as (bias, 0): ull biasP[(l*4+g)*16 + j]  (2 KB)
    __shared__ ull biasP[L_ * 4 * 16];
    extern __shared__ float hb[];        // 16 KB dynamic

    {
        float* wf = reinterpret_cast<float*>(wbuf4);
        for (int idx = threadIdx.x; idx < 8192; idx += blockDim.x) {
            int kin = idx & 3;
            int j   = (idx >> 2) & 15;
            int kc  = (idx >> 6) & 3;
            int g   = (idx >> 8) & 3;
            int mat = (idx >> 10) & 1;
            int l   = idx >> 11;
            int k   = kc * 4 + kin;
            float v;
            if (mat == 1) {
                v = Whh[l * 1024 + (g * 16 + j) * 16 + k];
            } else if (l == 0) {
                v = (k < IN_) ? Wih0[(g * 16 + j) * IN_ + k] : 0.0f;
            } else {
                v = Wih_rest[(l - 1) * 1024 + (g * 16 + j) * 16 + k];
            }
            wf[idx] = v;
        }
        for (int idx = threadIdx.x; idx < L_ * 4 * 16; idx += blockDim.x) {
            int j = idx & 15;
            int g = (idx >> 4) & 3;
            int l = idx >> 6;
            biasP[idx] = pack2(bih[l * 64 + g * 16 + j] + bhh[l * 64 + g * 16 + j], 0.0f);
        }
        for (int i = threadIdx.x; i < HB_TOTAL_F; i += blockDim.x) hb[i] = 0.0f;
    }
    __syncthreads();

    const int w    = threadIdx.x >> 5;
    const int grp  = (threadIdx.x >> 4) & 1;
    const int sub  = threadIdx.x & 15;               // owned hidden unit j
    const int b0   = blockIdx.x * 64 + (threadIdx.x >> 4) * 4;  // elems b0..b0+3
    const ulonglong2* __restrict__ wbuf2 = reinterpret_cast<const ulonglong2*>(wbuf4);

    float c_own[L_][4];
#pragma unroll
    for (int l = 0; l < L_; ++l)
#pragma unroll
        for (int e = 0; e < 4; ++e) c_own[l][e] = 0.0f;

    const float* hb_w = hb + w * HB_W;

    for (int t = 0; t < T_; ++t) {
        // layer-0 inputs as (x0,x1),(x2,x3) pairs (16B-aligned gmem loads)
        ulonglong2 xv[4];
#pragma unroll
        for (int e = 0; e < 4; ++e)
            xv[e] = *reinterpret_cast<const ulonglong2*>(x + ((long)(b0 + e) * T_ + t) * IN_);

#pragma unroll
        for (int l = 0; l < L_; ++l) {
            ull acc[4][4];   // [gate][e], halves = (even-k sum, odd-k sum)
#pragma unroll
            for (int g_ = 0; g_ < 4; ++g_) {
                ull bp = biasP[(l * 4 + g_) * 16 + sub];
#pragma unroll
                for (int e = 0; e < 4; ++e) acc[g_][e] = bp;
            }

            // ---- input projection ----
            if (l == 0) {
#pragma unroll
                for (int g_ = 0; g_ < 4; ++g_) {
                    ulonglong2 wv = wbuf2[(((0 * 2 + 0) * 4 + g_) * 4 + 0) * 16 + sub];
#pragma unroll
                    for (int e = 0; e < 4; ++e) {
                        acc[g_][e] = ffma2(wv.x, xv[e].x, acc[g_][e]);
                        acc[g_][e] = ffma2(wv.y, xv[e].y, acc[g_][e]);
                    }
                }
            } else {
                const float* hsrc = hb_w + (l - 1) * HB_L + grp * HB_GRP;
#pragma unroll
                for (int kc = 0; kc < 4; ++kc) {
                    ulonglong2 hp[4];
#pragma unroll
                    for (int e = 0; e < 4; ++e)
                        hp[e] = *reinterpret_cast<const ulonglong2*>(hsrc + e * HB_E + kc * 4);
#pragma unroll
                    for (int g_ = 0; g_ < 4; ++g_) {
                        ulonglong2 wv = wbuf2[(((l * 2 + 0) * 4 + g_) * 4 + kc) * 16 + sub];
#pragma unroll
                        for (int e = 0; e < 4; ++e) {
                            acc[g_][e] = ffma2(wv.x, hp[e].x, acc[g_][e]);
                            acc[g_][e] = ffma2(wv.y, hp[e].y, acc[g_][e]);
                        }
                    }
                }
            }

            // ---- recurrent projection (region l holds t-1 state) ----
            {
                const float* hsrc = hb_w + l * HB_L + grp * HB_GRP;
#pragma unroll
                for (int kc = 0; kc < 4; ++kc) {
                    ulonglong2 hp[4];
#pragma unroll
                    for (int e = 0; e < 4; ++e)
                        hp[e] = *reinterpret_cast<const ulonglong2*>(hsrc + e * HB_E + kc * 4);
#pragma unroll
                    for (int g_ = 0; g_ < 4; ++g_) {
                        ulonglong2 wv = wbuf2[(((l * 2 + 1) * 4 + g_) * 4 + kc) * 16 + sub];
#pragma unroll
                        for (int e = 0; e < 4; ++e) {
                            acc[g_][e] = ffma2(wv.x, hp[e].x, acc[g_][e]);
                            acc[g_][e] = ffma2(wv.y, hp[e].y, acc[g_][e]);
                        }
                    }
                }
            }

            // ---- horizontal add + activations + state update ----
            float hn[4];
#pragma unroll
            for (int e = 0; e < 4; ++e) {
                float lo, hi, ai, af, ag, ao;
                unpack2(acc[0][e], lo, hi); ai = lo + hi;
                unpack2(acc[1][e], lo, hi); af = lo + hi;
                unpack2(acc[2][e], lo, hi); ag = lo + hi;
                unpack2(acc[3][e], lo, hi); ao = lo + hi;
                float iv = sigmoidf_(ai);
                float fv = sigmoidf_(af);
                float gv = tanhf_(ag);
                float ov = sigmoidf_(ao);
                float cv = fmaf(fv, c_own[l][e], iv * gv);
                c_own[l][e] = cv;
                hn[e] = ov * tanhf_(cv);
            }

            // ---- publish new h (after all lanes finished reading old h) ----
            __syncwarp();
            {
                float* hdst = hb + w * HB_W + l * HB_L + grp * HB_GRP + sub;
#pragma unroll
                for (int e = 0; e < 4; ++e) hdst[e * HB_E] = hn[e];
            }
            __syncwarp();

            if (l == L_ - 1) {
                float4 v = make_float4(hn[0], hn[1], hn[2], hn[3]);
                *reinterpret_cast<float4*>(g_h3 + (long)(t * 16 + sub) * B_ + b0) = v;
            }
        }
    }
}

// =====================================================================
// MLP phase 1: partial hid sums over NCHUNK chunks of 200 rows.
// =====================================================================
__global__ void __launch_bounds__(256) mlp1_kernel(const float* __restrict__ W1)
{
    __shared__ float4 W1s[200 * 16];   // [mm][j4], 51.2 KB
    const int chunk = blockIdx.y;
    const int m0 = chunk * 200;
    {
        float* w = reinterpret_cast<float*>(W1s);
        for (int idx = threadIdx.x; idx < 200 * MLP_HID; idx += blockDim.x) {
            int mm = idx >> 6, j = idx & 63;
            w[idx] = W1[j * MLP_IN + m0 + mm];
        }
    }
    __syncthreads();

    const int jq = threadIdx.x & 3;
    const int bq = threadIdx.x >> 2;
    const int b0 = blockIdx.x * 256 + bq * 4;

    ull acc[8][4];
#pragma unroll
    for (int jp = 0; jp < 8; ++jp)
#pragma unroll
        for (int e = 0; e < 4; ++e) acc[jp][e] = 0ull;

    for (int mm = 0; mm < 200; ++mm) {
        float4 f = *reinterpret_cast<const float4*>(g_h3 + (long)(m0 + mm) * B_ + b0);
        ull f2[4] = { pack2(f.x, f.x), pack2(f.y, f.y), pack2(f.z, f.z), pack2(f.w, f.w) };
#pragma unroll
        for (int j4 = 0; j4 < 4; ++j4) {
            ulonglong2 wp = *reinterpret_cast<const ulonglong2*>(&W1s[mm * 16 + jq * 4 + j4]);
#pragma unroll
            for (int e = 0; e < 4; ++e) {
                acc[j4 * 2 + 0][e] = ffma2(wp.x, f2[e], acc[j4 * 2 + 0][e]);
                acc[j4 * 2 + 1][e] = ffma2(wp.y, f2[e], acc[j4 * 2 + 1][e]);
            }
        }
    }
#pragma unroll
    for (int jp = 0; jp < 8; ++jp) {
        float v0[4], v1[4];
#pragma unroll
        for (int e = 0; e < 4; ++e) unpack2(acc[jp][e], v0[e], v1[e]);
        int j = jq * 16 + jp * 2;
        *reinterpret_cast<float4*>(g_partial + ((long)chunk * MLP_HID + j) * B_ + b0) =
            make_float4(v0[0], v0[1], v0[2], v0[3]);
        *reinterpret_cast<float4*>(g_partial + ((long)chunk * MLP_HID + j + 1) * B_ + b0) =
            make_float4(v1[0], v1[1], v1[2], v1[3]);
    }
}

// =====================================================================
// MLP phase 2: reduce chunks, bias+relu, W2, write out [B, 28].
// =====================================================================
__global__ void __launch_bounds__(256) mlp2_kernel(
    const float* __restrict__ W2,   // [28, 64]
    const float* __restrict__ b1,   // [64]
    const float* __restrict__ b2,   // [28]
    float* __restrict__ out)        // [B, 28]
{
    __shared__ float W2s[MLP_OUT * MLP_HID];
    __shared__ float b1s[MLP_HID];
    __shared__ float b2s[MLP_OUT];
    for (int idx = threadIdx.x; idx < MLP_OUT * MLP_HID; idx += blockDim.x)
        W2s[idx] = W2[idx];
    if (threadIdx.x < MLP_HID) b1s[threadIdx.x] = b1[threadIdx.x];
    if (threadIdx.x < MLP_OUT) b2s[threadIdx.x] = b2[threadIdx.x];
    __syncthreads();

    const int b = blockIdx.x * 256 + threadIdx.x;
    float hid[MLP_HID];
#pragma unroll
    for (int j = 0; j < MLP_HID; ++j) hid[j] = b1s[j];

    for (int ch = 0; ch < NCHUNK; ++ch) {
#pragma unroll
        for (int j = 0; j < MLP_HID; ++j)
            hid[j] += g_partial[((long)ch * MLP_HID + j) * B_ + b];
    }
#pragma unroll
    for (int j = 0; j < MLP_HID; ++j) hid[j] = fmaxf(hid[j], 0.0f);

#pragma unroll
    for (int o = 0; o < MLP_OUT; ++o) {
        float a = b2s[o];
#pragma unroll
        for (int j = 0; j < MLP_HID; ++j)
            a = fmaf(hid[j], W2s[o * MLP_HID + j], a);
        out[(long)b * MLP_OUT + o] = a;
    }
}

// =====================================================================
extern "C" void kernel_launch(void* const* d_in, const int* in_sizes, int n_in,
                              void* d_out, int out_size)
{
    const float* x        = (const float*)d_in[0];
    const float* Wih0     = (const float*)d_in[1];
    const float* Wih_rest = (const float*)d_in[2];
    const float* Whh      = (const float*)d_in[3];
    const float* bih      = (const float*)d_in[4];
    const float* bhh      = (const float*)d_in[5];
    const float* W1       = (const float*)d_in[6];
    const float* b1       = (const float*)d_in[7];
    const float* W2       = (const float*)d_in[8];
    const float* b2       = (const float*)d_in[9];
    float* out = (float*)d_out;

    // static (34 KB) + dynamic (16 KB) smem exceeds the 48 KB opt-out
    // limit -> must raise the dynamic limit (capture-safe, no allocation).
    cudaFuncSetAttribute(lstm_kernel, cudaFuncAttributeMaxDynamicSharedMemorySize,
                         HB_TOTAL_F * (int)sizeof(float));
    lstm_kernel<<<128, 256, HB_TOTAL_F * sizeof(float)>>>(x, Wih0, Wih_rest, Whh, bih, bhh);
    mlp1_kernel<<<dim3(32, NCHUNK), 256>>>(W1);
    mlp2_kernel<<<32, 256>>>(W2, b1, b2, out);
}

// round 11
// speedup vs baseline: 1.2188x; 1.0912x over previous
#include <cuda_runtime.h>
#include <cuda_bf16.h>

#define B_  8192
#define T_  200
#define IN_ 4
#define H_  16
#define L_  4
#define MLP_IN  (H_ * T_)   // 3200
#define MLP_HID 64
#define MLP_OUT 28
#define NCHUNK  16          // mlp1 K-chunks (200 rows each)

typedef unsigned long long ull;

// ---------------- scratch (no allocations allowed) ----------------
__device__ float g_h3[(long)MLP_IN * B_];                 // [m][b]
__device__ float g_partial[NCHUNK * MLP_HID * B_];        // [chunk][j][b]

// ---------------- packed f32x2 helpers ----------------
__device__ __forceinline__ ull pack2(float lo, float hi) {
    ull r; asm("mov.b64 %0, {%1, %2};" : "=l"(r) : "f"(lo), "f"(hi)); return r;
}
__device__ __forceinline__ void unpack2(ull v, float& lo, float& hi) {
    asm("mov.b64 {%0, %1}, %2;" : "=f"(lo), "=f"(hi) : "l"(v));
}
__device__ __forceinline__ ull ffma2(ull a, ull b, ull c) {
    ull d; asm("fma.rn.f32x2 %0, %1, %2, %3;" : "=l"(d) : "l"(a), "l"(b), "l"(c)); return d;
}

// ---------------- activations (fp32, overflow-safe) ----------------
__device__ __forceinline__ float sigmoidf_(float x) {
    return __fdividef(1.0f, 1.0f + __expf(-x));
}
__device__ __forceinline__ float tanhf_(float x) {
    float e = __expf(-2.0f * fabsf(x));           // in (0, 1], never overflows
    float t = __fdividef(1.0f - e, 1.0f + e);
    return copysignf(t, x);
}

// h ring buffer: float hbuf[parity(2)][layer(4)][eg(8)][row 20 (16 used, pad 4)]
#define HB_ROW  20
#define HB_SLOT (8 * HB_ROW)          // one (parity, layer) slot
#define HB_TOTAL (2 * 4 * HB_SLOT)    // 1280 floats = 5 KB

// =====================================================================
// Layer-pipelined LSTM: CTA = 4 warps = 4 layers (one pipeline), 8 elems.
// Warp l (rotated by bid) holds layer-l weights ENTIRELY IN REGISTERS
// (f32x2 k-pairs) and computes timestep t = i - l at iteration i.
// h exchanged via double-buffered smem; one __syncthreads per iteration.
// 1024 CTAs x 128 threads, 2 CTAs/SM.
// Lane: sub = lane&15 (owned unit j), grp = lane>>4 (4 elems each).
// =====================================================================
__global__ void __launch_bounds__(128, 2) lstm_kernel(
    const float* __restrict__ x,         // [B, T, IN]
    const float* __restrict__ Wih0,      // [64, 4]
    const float* __restrict__ Wih_rest,  // [3, 64, 16]
    const float* __restrict__ Whh,       // [4, 64, 16]
    const float* __restrict__ bih,       // [4, 64]
    const float* __restrict__ bhh)       // [4, 64]
{
    __shared__ __align__(16) float hbuf[HB_TOTAL];

    const int wid = threadIdx.x >> 5;
    const int lane = threadIdx.x & 31;
    const int sub = lane & 15;
    const int grp = lane >> 4;
    const int l   = (wid + (int)blockIdx.x) & 3;          // layer rotation
    const int b0  = (int)blockIdx.x * 8 + grp * 4;        // elems b0..b0+3

    for (int i = threadIdx.x; i < HB_TOTAL; i += blockDim.x) hbuf[i] = 0.0f;

    // ---- load this layer's weights into registers (k-pair packed) ----
    ull Wrec[4][8];   // [gate][kpair]
    ull Win[4][8];
    ull biasR[4];
#pragma unroll
    for (int g = 0; g < 4; ++g) {
        const float* rsrc = Whh + l * 1024 + (g * 16 + sub) * 16;
#pragma unroll
        for (int kc = 0; kc < 4; ++kc) {
            ulonglong2 v = *reinterpret_cast<const ulonglong2*>(rsrc + kc * 4);
            Wrec[g][2 * kc] = v.x; Wrec[g][2 * kc + 1] = v.y;
        }
        if (l == 0) {
            ulonglong2 v = *reinterpret_cast<const ulonglong2*>(Wih0 + (g * 16 + sub) * IN_);
            Win[g][0] = v.x; Win[g][1] = v.y;
#pragma unroll
            for (int kp = 2; kp < 8; ++kp) Win[g][kp] = 0ull;
        } else {
            const float* isrc = Wih_rest + (l - 1) * 1024 + (g * 16 + sub) * 16;
#pragma unroll
            for (int kc = 0; kc < 4; ++kc) {
                ulonglong2 v = *reinterpret_cast<const ulonglong2*>(isrc + kc * 4);
                Win[g][2 * kc] = v.x; Win[g][2 * kc + 1] = v.y;
            }
        }
        biasR[g] = pack2(bih[l * 64 + g * 16 + sub] + bhh[l * 64 + g * 16 + sub], 0.0f);
    }

    float c_own[4] = {0.0f, 0.0f, 0.0f, 0.0f};
    __syncthreads();

    for (int i = 0; i < T_ + L_ - 1; ++i) {
        const int p = i & 1;
        const int t = i - l;
        const bool active = ((unsigned)t < (unsigned)T_);

        float hn[4];
        if (active) {
            ull acc[4][4];   // [gate][e], halves = (even-k, odd-k) partials
#pragma unroll
            for (int g = 0; g < 4; ++g)
#pragma unroll
                for (int e = 0; e < 4; ++e) acc[g][e] = biasR[g];

            // ---- input projection ----
            if (l == 0) {
                ulonglong2 xv[4];
#pragma unroll
                for (int e = 0; e < 4; ++e)
                    xv[e] = *reinterpret_cast<const ulonglong2*>(
                        x + (long)(b0 + e) * (T_ * IN_) + t * IN_);
#pragma unroll
                for (int g = 0; g < 4; ++g)
#pragma unroll
                    for (int e = 0; e < 4; ++e) {
                        acc[g][e] = ffma2(Win[g][0], xv[e].x, acc[g][e]);
                        acc[g][e] = ffma2(Win[g][1], xv[e].y, acc[g][e]);
                    }
            } else {
                const float* hsrc = hbuf + ((1 - p) * 4 + (l - 1)) * HB_SLOT;
#pragma unroll
                for (int kc = 0; kc < 4; ++kc) {
                    ulonglong2 hv[4];
#pragma unroll
                    for (int e = 0; e < 4; ++e)
                        hv[e] = *reinterpret_cast<const ulonglong2*>(
                            hsrc + (grp * 4 + e) * HB_ROW + kc * 4);
#pragma unroll
                    for (int g = 0; g < 4; ++g)
#pragma unroll
                        for (int e = 0; e < 4; ++e) {
                            acc[g][e] = ffma2(Win[g][2 * kc],     hv[e].x, acc[g][e]);
                            acc[g][e] = ffma2(Win[g][2 * kc + 1], hv[e].y, acc[g][e]);
                        }
                }
            }

            // ---- recurrent projection (own layer's h at t-1) ----
            {
                const float* hsrc = hbuf + ((1 - p) * 4 + l) * HB_SLOT;
#pragma unroll
                for (int kc = 0; kc < 4; ++kc) {
                    ulonglong2 hv[4];
#pragma unroll
                    for (int e = 0; e < 4; ++e)
                        hv[e] = *reinterpret_cast<const ulonglong2*>(
                            hsrc + (grp * 4 + e) * HB_ROW + kc * 4);
#pragma unroll
                    for (int g = 0; g < 4; ++g)
#pragma unroll
                        for (int e = 0; e < 4; ++e) {
                            acc[g][e] = ffma2(Wrec[g][2 * kc],     hv[e].x, acc[g][e]);
                            acc[g][e] = ffma2(Wrec[g][2 * kc + 1], hv[e].y, acc[g][e]);
                        }
                }
            }

            // ---- horizontal add + activations + state update ----
#pragma unroll
            for (int e = 0; e < 4; ++e) {
                float lo, hi, ai, af, ag, ao;
                unpack2(acc[0][e], lo, hi); ai = lo + hi;
                unpack2(acc[1][e], lo, hi); af = lo + hi;
                unpack2(acc[2][e], lo, hi); ag = lo + hi;
                unpack2(acc[3][e], lo, hi); ao = lo + hi;
                float iv = sigmoidf_(ai);
                float fv = sigmoidf_(af);
                float gv = tanhf_(ag);
                float ov = sigmoidf_(ao);
                float cv = fmaf(fv, c_own[e], iv * gv);
                c_own[e] = cv;
                hn[e] = ov * tanhf_(cv);
            }

            // ---- publish new h into buf[p] slot l ----
            {
                float* hdst = hbuf + (p * 4 + l) * HB_SLOT;
#pragma unroll
                for (int e = 0; e < 4; ++e)
                    hdst[(grp * 4 + e) * HB_ROW + sub] = hn[e];
            }
            if (l == L_ - 1) {
                float4 v = make_float4(hn[0], hn[1], hn[2], hn[3]);
                *reinterpret_cast<float4*>(g_h3 + (long)(t * 16 + sub) * B_ + b0) = v;
            }
        }
        __syncthreads();
    }
}

// =====================================================================
// MLP phase 1: partial hid sums over NCHUNK chunks of 200 rows.
// =====================================================================
__global__ void __launch_bounds__(256) mlp1_kernel(const float* __restrict__ W1)
{
    __shared__ float4 W1s[200 * 16];   // [mm][j4], 51.2 KB
    const int chunk = blockIdx.y;
    const int m0 = chunk * 200;
    {
        float* w = reinterpret_cast<float*>(W1s);
        for (int idx = threadIdx.x; idx < 200 * MLP_HID; idx += blockDim.x) {
            int mm = idx >> 6, j = idx & 63;
            w[idx] = W1[j * MLP_IN + m0 + mm];
        }
    }
    __syncthreads();

    const int jq = threadIdx.x & 3;
    const int bq = threadIdx.x >> 2;
    const int b0 = blockIdx.x * 256 + bq * 4;

    ull acc[8][4];
#pragma unroll
    for (int jp = 0; jp < 8; ++jp)
#pragma unroll
        for (int e = 0; e < 4; ++e) acc[jp][e] = 0ull;

    for (int mm = 0; mm < 200; ++mm) {
        float4 f = *reinterpret_cast<const float4*>(g_h3 + (long)(m0 + mm) * B_ + b0);
        ull f2[4] = { pack2(f.x, f.x), pack2(f.y, f.y), pack2(f.z, f.z), pack2(f.w, f.w) };
#pragma unroll
        for (int j4 = 0; j4 < 4; ++j4) {
            ulonglong2 wp = *reinterpret_cast<const ulonglong2*>(&W1s[mm * 16 + jq * 4 + j4]);
#pragma unroll
            for (int e = 0; e < 4; ++e) {
                acc[j4 * 2 + 0][e] = ffma2(wp.x, f2[e], acc[j4 * 2 + 0][e]);
                acc[j4 * 2 + 1][e] = ffma2(wp.y, f2[e], acc[j4 * 2 + 1][e]);
            }
        }
    }
#pragma unroll
    for (int jp = 0; jp < 8; ++jp) {
        float v0[4], v1[4];
#pragma unroll
        for (int e = 0; e < 4; ++e) unpack2(acc[jp][e], v0[e], v1[e]);
        int j = jq * 16 + jp * 2;
        *reinterpret_cast<float4*>(g_partial + ((long)chunk * MLP_HID + j) * B_ + b0) =
            make_float4(v0[0], v0[1], v0[2], v0[3]);
        *reinterpret_cast<float4*>(g_partial + ((long)chunk * MLP_HID + j + 1) * B_ + b0) =
            make_float4(v1[0], v1[1], v1[2], v1[3]);
    }
}

// =====================================================================
// MLP phase 2: reduce chunks, bias+relu, W2, write out [B, 28].
// =====================================================================
__global__ void __launch_bounds__(256) mlp2_kernel(
    const float* __restrict__ W2,   // [28, 64]
    const float* __restrict__ b1,   // [64]
    const float* __restrict__ b2,   // [28]
    float* __restrict__ out)        // [B, 28]
{
    __shared__ float W2s[MLP_OUT * MLP_HID];
    __shared__ float b1s[MLP_HID];
    __shared__ float b2s[MLP_OUT];
    for (int idx = threadIdx.x; idx < MLP_OUT * MLP_HID; idx += blockDim.x)
        W2s[idx] = W2[idx];
    if (threadIdx.x < MLP_HID) b1s[threadIdx.x] = b1[threadIdx.x];
    if (threadIdx.x < MLP_OUT) b2s[threadIdx.x] = b2[threadIdx.x];
    __syncthreads();

    const int b = blockIdx.x * 256 + threadIdx.x;
    float hid[MLP_HID];
#pragma unroll
    for (int j = 0; j < MLP_HID; ++j) hid[j] = b1s[j];

    for (int ch = 0; ch < NCHUNK; ++ch) {
#pragma unroll
        for (int j = 0; j < MLP_HID; ++j)
            hid[j] += g_partial[((long)ch * MLP_HID + j) * B_ + b];
    }
#pragma unroll
    for (int j = 0; j < MLP_HID; ++j) hid[j] = fmaxf(hid[j], 0.0f);

#pragma unroll
    for (int o = 0; o < MLP_OUT; ++o) {
        float a = b2s[o];
#pragma unroll
        for (int j = 0; j < MLP_HID; ++j)
            a = fmaf(hid[j], W2s[o * MLP_HID + j], a);
        out[(long)b * MLP_OUT + o] = a;
    }
}

// =====================================================================
extern "C" void kernel_launch(void* const* d_in, const int* in_sizes, int n_in,
                              void* d_out, int out_size)
{
    const float* x        = (const float*)d_in[0];
    const float* Wih0     = (const float*)d_in[1];
    const float* Wih_rest = (const float*)d_in[2];
    const float* Whh      = (const float*)d_in[3];
    const float* bih      = (const float*)d_in[4];
    const float* bhh      = (const float*)d_in[5];
    const float* W1       = (const float*)d_in[6];
    const float* b1       = (const float*)d_in[7];
    const float* W2       = (const float*)d_in[8];
    const float* b2       = (const float*)d_in[9];
    float* out = (float*)d_out;

    lstm_kernel<<<1024, 128>>>(x, Wih0, Wih_rest, Whh, bih, bhh);
    mlp1_kernel<<<dim3(32, NCHUNK), 256>>>(W1);
    mlp2_kernel<<<32, 256>>>(W2, b1, b2, out);
}